// round 16
// baseline (speedup 1.0000x reference)
#include <cuda_runtime.h>
#include <cuda_fp16.h>
#include <cstdint>

#define E_DIM 1024
#define H_DIM 16
#define D_DIM 64
#define SEQ 2048
#define NB 2
#define NHTOT (NB * H_DIM)
#define XSZ (NB * SEQ * E_DIM)
#define WSZ (E_DIM * E_DIM)
#define QKV_SZ (NHTOT * SEQ * D_DIM)

// Single fp16 inputs
__device__ __half g_xh[3 * XSZ];
__device__ __half g_wh[3 * WSZ];
// Q full [nh][t][d]; V full [nh][t][d] (for vmean); K/V compressed [nh][j][d]
__device__ __half g_qh[QKV_SZ];
__device__ __half g_vh[QKV_SZ];
__device__ __half g_khc[QKV_SZ];   // tail rows stay zero (never written)
__device__ __half g_vhc[QKV_SZ];
// Compression metadata
__device__ int g_pos[NB * SEQ];    // original t of j-th visible key (tail = 1<<29)
__device__ int g_pref[NB * SEQ];   // # visible keys with index <= t
__device__ int g_slot[NB * SEQ];   // compressed slot of row t, or -1 if masked
__device__ int g_cnt[NB];
// vmean two-stage
__device__ float g_vpart[NHTOT * 8 * D_DIM];
__device__ float g_vmean[NHTOT * D_DIM];

#define SC 0.18033688f     // 0.125 * log2(e)
#define NEGB (-1.5e9f)

// ---------------------------------------------------------------------------
// Helpers
// ---------------------------------------------------------------------------
__device__ __forceinline__ void mma_f16(float c[4], const uint32_t a[4],
                                        uint32_t b0, uint32_t b1) {
    asm("mma.sync.aligned.m16n8k16.row.col.f32.f16.f16.f32 "
        "{%0,%1,%2,%3}, {%4,%5,%6,%7}, {%8,%9}, {%0,%1,%2,%3};"
        : "+f"(c[0]), "+f"(c[1]), "+f"(c[2]), "+f"(c[3])
        : "r"(a[0]), "r"(a[1]), "r"(a[2]), "r"(a[3]), "r"(b0), "r"(b1));
}

__device__ __forceinline__ void ldmx4(uint32_t r[4], uint32_t addr) {
    asm volatile("ldmatrix.sync.aligned.m8n8.x4.shared.b16 {%0,%1,%2,%3}, [%4];"
                 : "=r"(r[0]), "=r"(r[1]), "=r"(r[2]), "=r"(r[3]) : "r"(addr));
}
__device__ __forceinline__ void ldmx4t(uint32_t r[4], uint32_t addr) {
    asm volatile("ldmatrix.sync.aligned.m8n8.x4.trans.shared.b16 {%0,%1,%2,%3}, [%4];"
                 : "=r"(r[0]), "=r"(r[1]), "=r"(r[2]), "=r"(r[3]) : "r"(addr));
}

__device__ __forceinline__ uint32_t smem_u32(const void* p) {
    uint32_t a;
    asm("{ .reg .u64 t; cvta.to.shared.u64 t, %1; cvt.u32.u64 %0, t; }"
        : "=r"(a) : "l"(p));
    return a;
}

__device__ __forceinline__ void cp16(uint32_t dst, const void* src) {
    asm volatile("cp.async.cg.shared.global [%0], [%1], 16;" :: "r"(dst), "l"(src));
}
#define CP_COMMIT() asm volatile("cp.async.commit_group;" ::: "memory")
#define CP_WAIT0() asm volatile("cp.async.wait_group 0;" ::: "memory")
#define CP_WAIT1() asm volatile("cp.async.wait_group 1;" ::: "memory")

__device__ __forceinline__ uint32_t pack_h(float x, float y) {
    __half2 h = __floats2half2_rn(x, y);
    return *reinterpret_cast<uint32_t*>(&h);
}

// ---------------------------------------------------------------------------
// Fused conversion: six fp32->fp16 tensors; 2 float4 per thread.
// ---------------------------------------------------------------------------
#define XB (XSZ / 8 / 256)
#define WB (WSZ / 8 / 256)

__global__ __launch_bounds__(256) void conv_all_kernel(
    const float* __restrict__ q, const float* __restrict__ k,
    const float* __restrict__ v, const float* __restrict__ wq,
    const float* __restrict__ wk, const float* __restrict__ wv)
{
    const int b = blockIdx.x;
    const float* src;
    __half* dst;
    int local;
    if (b < 3 * XB) {
        const int z = b / XB;
        local = b - z * XB;
        src = (z == 0) ? q : (z == 1) ? k : v;
        dst = g_xh + (size_t)z * XSZ;
    } else {
        const int bb = b - 3 * XB;
        const int z = bb / WB;
        local = bb - z * WB;
        src = (z == 0) ? wq : (z == 1) ? wk : wv;
        dst = g_wh + (size_t)z * WSZ;
    }
#pragma unroll
    for (int r = 0; r < 2; r++) {
        const int i = local * 512 + r * 256 + threadIdx.x;
        float4 val = ((const float4*)src)[i];
        ((uint32_t*)dst)[2 * i + 0] = pack_h(val.x, val.y);
        ((uint32_t*)dst)[2 * i + 1] = pack_h(val.z, val.w);
    }
}

// ---------------------------------------------------------------------------
// Prefix scan of pad mask -> g_pos / g_pref / g_slot / g_cnt.
// ---------------------------------------------------------------------------
__global__ __launch_bounds__(1024) void scan_kernel(const int* __restrict__ pad)
{
    const int n = blockIdx.x;
    const int tid = threadIdx.x;
    const int lane = tid & 31;
    const int wid = tid >> 5;
    const int e0 = pad[n * SEQ + 2 * tid] != 0;
    const int e1 = pad[n * SEQ + 2 * tid + 1] != 0;
    const int s = e0 + e1;
    int v = s;
#pragma unroll
    for (int off = 1; off < 32; off <<= 1) {
        int t = __shfl_up_sync(0xffffffffu, v, off);
        if (lane >= off) v += t;
    }
    __shared__ int wsum[32];
    if (lane == 31) wsum[wid] = v;
    __syncthreads();
    if (wid == 0) {
        int t = wsum[lane];
#pragma unroll
        for (int off = 1; off < 32; off <<= 1) {
            int u = __shfl_up_sync(0xffffffffu, t, off);
            if (lane >= off) t += u;
        }
        wsum[lane] = t;
    }
    __syncthreads();
    const int total = wsum[31];
    const int incl = (wid ? wsum[wid - 1] : 0) + v;
    const int excl = incl - s;
    if (e0) g_pos[n * SEQ + excl] = 2 * tid;
    if (e1) g_pos[n * SEQ + excl + e0] = 2 * tid + 1;
    g_pref[n * SEQ + 2 * tid] = excl + e0;
    g_pref[n * SEQ + 2 * tid + 1] = incl;
    g_slot[n * SEQ + 2 * tid] = e0 ? excl : -1;
    g_slot[n * SEQ + 2 * tid + 1] = e1 ? (excl + e0) : -1;
    if (tid == 1023) g_cnt[n] = total;
    __syncthreads();
    for (int i = total + tid; i < SEQ; i += 1024)
        g_pos[n * SEQ + i] = (1 << 29);
}

// ---------------------------------------------------------------------------
// Projection GEMM. z=0: Q (all rows). z=2: V (all rows; full + compressed).
// z=1: K computed ONLY for visible rows, in compressed index space — block
// covers compressed rows [i0&2047, +128) of batch i0>>11 via rowSrc gather;
// empty blocks exit early.
// ---------------------------------------------------------------------------
__global__ __launch_bounds__(256) void proj_mma_kernel(
    const float* __restrict__ bq, const float* __restrict__ bk,
    const float* __restrict__ bv)
{
    __shared__ __half Ah[128][40];
    __shared__ __half Bh[128][40];
    __shared__ int rowSrc[128];

    const int tid = threadIdx.x;
    const int w = tid >> 5;
    const int lane = tid & 31;
    const int g = lane >> 2;
    const int tq = lane & 3;
    const int z = blockIdx.z;
    const int j0 = blockIdx.x * 128;
    const int i0 = blockIdx.y * 128;
    const int mrow = (w & 3) * 32;
    const int ncol = (w >> 2) * 64;

    const int nbat = i0 >> 11;
    const int jbase = i0 & 2047;
    int kcnt = 0;
    if (z == 1) {
        kcnt = g_cnt[nbat];
        if (jbase >= kcnt) return;   // uniform across block
    }
    if (tid < 128) {
        int sr;
        if (z == 1) {
            const int j = jbase + tid;
            sr = nbat * SEQ + ((j < kcnt) ? g_pos[nbat * SEQ + j] : 0);
        } else {
            sr = i0 + tid;
        }
        rowSrc[tid] = sr;
    }
    __syncthreads();

    const __half* xh = g_xh + (size_t)z * XSZ;
    const __half* wh = g_wh + (size_t)z * WSZ;
    const float* bias = (z == 0) ? bq : (z == 1) ? bk : bv;

    float c[2][8][4];
#pragma unroll
    for (int mt = 0; mt < 2; mt++)
#pragma unroll
        for (int nt = 0; nt < 8; nt++)
#pragma unroll
            for (int u = 0; u < 4; u++) c[mt][nt][u] = 0.0f;

    for (int k0 = 0; k0 < E_DIM; k0 += 32) {
#pragma unroll
        for (int it = 0; it < 2; it++) {
            const int idx = tid + it * 256;
            const int row = idx >> 2;
            const int seg = (idx & 3) * 8;
            const size_t ga = (size_t)rowSrc[row] * E_DIM + k0 + seg;
            const size_t gb = (size_t)(j0 + row) * E_DIM + k0 + seg;
            *(uint4*)&Ah[row][seg] = *(const uint4*)(xh + ga);
            *(uint4*)&Bh[row][seg] = *(const uint4*)(wh + gb);
        }
        __syncthreads();

#pragma unroll
        for (int kc = 0; kc < 32; kc += 16) {
            uint32_t a[2][4];
#pragma unroll
            for (int mt = 0; mt < 2; mt++) {
                const int r0 = mrow + mt * 16 + g;
                a[mt][0] = *(const uint32_t*)&Ah[r0][kc + 2 * tq];
                a[mt][1] = *(const uint32_t*)&Ah[r0 + 8][kc + 2 * tq];
                a[mt][2] = *(const uint32_t*)&Ah[r0][kc + 2 * tq + 8];
                a[mt][3] = *(const uint32_t*)&Ah[r0 + 8][kc + 2 * tq + 8];
            }
#pragma unroll
            for (int nt = 0; nt < 8; nt++) {
                const int nr = ncol + nt * 8 + g;
                uint32_t b0 = *(const uint32_t*)&Bh[nr][kc + 2 * tq];
                uint32_t b1 = *(const uint32_t*)&Bh[nr][kc + 2 * tq + 8];
#pragma unroll
                for (int mt = 0; mt < 2; mt++)
                    mma_f16(c[mt][nt], a[mt], b0, b1);
            }
        }
        __syncthreads();
    }

    // Epilogue
#pragma unroll
    for (int mt = 0; mt < 2; mt++) {
        const int r0 = i0 + mrow + mt * 16 + g;
        const int r1 = r0 + 8;
        const int n0 = r0 >> 11, t0a = r0 & 2047;
        const int n1 = r1 >> 11, t1a = r1 & 2047;
        int sl0 = 0, sl1 = 0;
        if (z == 2) {
            sl0 = g_slot[n0 * SEQ + t0a];
            sl1 = g_slot[n1 * SEQ + t1a];
        }
#pragma unroll
        for (int nt = 0; nt < 8; nt++) {
            const int gj = j0 + ncol + nt * 8 + 2 * tq;
            const int h = gj >> 6;
            const int dd = gj & 63;
            const float b0v = bias[gj], b1v = bias[gj + 1];
            const float v00 = c[mt][nt][0] + b0v, v01 = c[mt][nt][1] + b1v;
            const float v10 = c[mt][nt][2] + b0v, v11 = c[mt][nt][3] + b1v;
            if (z == 0) {
                const size_t a0 = ((size_t)(n0 * H_DIM + h) * SEQ + t0a) * D_DIM + dd;
                const size_t a1 = ((size_t)(n1 * H_DIM + h) * SEQ + t1a) * D_DIM + dd;
                *(uint32_t*)(g_qh + a0) = pack_h(v00, v01);
                *(uint32_t*)(g_qh + a1) = pack_h(v10, v11);
            } else if (z == 1) {
                // rows ARE compressed indices: t0a/t1a = j within batch nbat
                if (t0a < kcnt)
                    *(uint32_t*)(g_khc + ((size_t)(nbat * H_DIM + h) * SEQ + t0a) * D_DIM + dd) =
                        pack_h(v00, v01);
                if (t1a < kcnt)
                    *(uint32_t*)(g_khc + ((size_t)(nbat * H_DIM + h) * SEQ + t1a) * D_DIM + dd) =
                        pack_h(v10, v11);
            } else {
                const size_t a0 = ((size_t)(n0 * H_DIM + h) * SEQ + t0a) * D_DIM + dd;
                const size_t a1 = ((size_t)(n1 * H_DIM + h) * SEQ + t1a) * D_DIM + dd;
                const uint32_t p0 = pack_h(v00, v01);
                const uint32_t p1 = pack_h(v10, v11);
                *(uint32_t*)(g_vh + a0) = p0;
                *(uint32_t*)(g_vh + a1) = p1;
                if (sl0 >= 0)
                    *(uint32_t*)(g_vhc + ((size_t)(n0 * H_DIM + h) * SEQ + sl0) * D_DIM + dd) = p0;
                if (sl1 >= 0)
                    *(uint32_t*)(g_vhc + ((size_t)(n1 * H_DIM + h) * SEQ + sl1) * D_DIM + dd) = p1;
            }
        }
    }
}

// ---------------------------------------------------------------------------
// vmean stage 1: vectorized. grid (NHTOT, 8); 256-row slab per block.
// Thread (rg, dseg) sums 8 rows x 8 d-channels via uint4 loads; smem fold.
// ---------------------------------------------------------------------------
__global__ __launch_bounds__(256) void vmean1_kernel()
{
    __shared__ float red[32][65];
    const int nh = blockIdx.x;
    const int slab = blockIdx.y;
    const int rg = threadIdx.x >> 3;          // 0..31
    const int dseg = (threadIdx.x & 7) * 8;   // 0..56
    float f[8];
#pragma unroll
    for (int i = 0; i < 8; i++) f[i] = 0.0f;
#pragma unroll
    for (int r = 0; r < 8; r++) {
        const int t = slab * 256 + rg * 8 + r;
        uint4 v = *(const uint4*)(g_vh + ((size_t)nh * SEQ + t) * D_DIM + dseg);
        const __half2* h2 = (const __half2*)&v;
#pragma unroll
        for (int i = 0; i < 4; i++) {
            f[2 * i + 0] += __half2float(h2[i].x);
            f[2 * i + 1] += __half2float(h2[i].y);
        }
    }
#pragma unroll
    for (int i = 0; i < 8; i++) red[rg][dseg + i] = f[i];
    __syncthreads();
    if (threadIdx.x < 64) {
        float tot = 0.0f;
#pragma unroll
        for (int r = 0; r < 32; r++) tot += red[r][threadIdx.x];
        g_vpart[(nh * 8 + slab) * D_DIM + threadIdx.x] = tot;
    }
}

__global__ __launch_bounds__(64) void vmean2_kernel()
{
    const int nh = blockIdx.x;
    const int dd = threadIdx.x;
    float tot = 0.0f;
#pragma unroll
    for (int s = 0; s < 8; s++)
        tot += g_vpart[(nh * 8 + s) * D_DIM + dd];
    g_vmean[nh * D_DIM + dd] = tot * (1.0f / (float)SEQ);
}

// ---------------------------------------------------------------------------
// Flash attention on compressed keys — R13-R15 kernel VERBATIM.
// ---------------------------------------------------------------------------
#define AT_STRIDE 72
#define AT_T (64 * AT_STRIDE)
#define AT_BUF (2 * AT_T)
#define AT_POS_OFF (2 * AT_BUF * 2)
#define AT_SMEM (AT_POS_OFF + 2 * 64 * 4)

__global__ __launch_bounds__(256) void attn_mma_kernel(float* __restrict__ out)
{
    extern __shared__ __half smh[];
    const uint32_t smb = smem_u32(smh);

    const int tid = threadIdx.x;
    const int w = tid >> 5;
    const int lane = tid & 31;
    const int g = lane >> 2;
    const int tq = lane & 3;
    const int qt = (int)(gridDim.x - 1 - blockIdx.x);
    const int nh = blockIdx.y;
    const int nb = nh >> 4;
    const int h = nh & 15;
    const int i0 = qt * 128;
    const int qr0 = i0 + w * 16 + g;
    const int qr1 = qr0 + 8;

    const uint32_t lcoK =
        (uint32_t)((((lane >> 4) & 1) * 8 + (lane & 7)) * AT_STRIDE +
                   ((lane >> 3) & 1) * 8);
    const uint32_t lcoV =
        (uint32_t)(((lane & 7) + ((lane >> 3) & 1) * 8) * AT_STRIDE +
                   ((lane >> 4) & 1) * 8);

    uint32_t qf[4][4];
    {
        const size_t b0 = ((size_t)nh * SEQ + qr0) * D_DIM;
        const size_t b1 = ((size_t)nh * SEQ + qr1) * D_DIM;
#pragma unroll
        for (int kd = 0; kd < 4; kd++) {
            const int cO = kd * 16 + 2 * tq;
            qf[kd][0] = *(const uint32_t*)(g_qh + b0 + cO);
            qf[kd][1] = *(const uint32_t*)(g_qh + b1 + cO);
            qf[kd][2] = *(const uint32_t*)(g_qh + b0 + cO + 8);
            qf[kd][3] = *(const uint32_t*)(g_qh + b1 + cO + 8);
        }
    }

    auto load_tiles = [&](int buf, int t0) {
        const uint32_t base = smb + buf * (AT_BUF * 2);
        const __half* kh = g_khc + ((size_t)nh * SEQ + t0) * D_DIM;
        const __half* vh = g_vhc + ((size_t)nh * SEQ + t0) * D_DIM;
#pragma unroll
        for (int it = 0; it < 2; it++) {
            const int idx = tid + it * 256;
            const int row = idx >> 3;
            const int seg = (idx & 7) * 8;
            const uint32_t so = (uint32_t)(row * AT_STRIDE + seg) * 2;
            cp16(base + 0 * AT_T * 2 + so, kh + (size_t)row * D_DIM + seg);
            cp16(base + 1 * AT_T * 2 + so, vh + (size_t)row * D_DIM + seg);
        }
        if (tid < 16)
            cp16(smb + AT_POS_OFF + buf * 256 + tid * 16,
                 g_pos + nb * SEQ + t0 + tid * 4);
        CP_COMMIT();
    };

    float o[8][4];
#pragma unroll
    for (int dt = 0; dt < 8; dt++)
#pragma unroll
        for (int u = 0; u < 4; u++) o[dt][u] = 0.0f;
    float m0 = -1e9f, m1 = -1e9f, l0 = 0.0f, l1 = 0.0f;

    const int nvis = g_pref[nb * SEQ + i0 + 127];
    const int ntiles = (nvis + 63) >> 6;

    if (ntiles > 0) {
        load_tiles(0, 0);

        for (int j = 0; j < ntiles; j++) {
            if (j < ntiles - 1) load_tiles((j + 1) & 1, (j + 1) * 64);
            if (j < ntiles - 1) { CP_WAIT1(); } else { CP_WAIT0(); }
            __syncthreads();

            const uint32_t Kb = smb + (j & 1) * (AT_BUF * 2);
            const uint32_t Vb = Kb + AT_T * 2;
            const int* posS =
                (const int*)((const char*)smh + AT_POS_OFF + (j & 1) * 256);

            float s[8][4];
#pragma unroll
            for (int nt = 0; nt < 8; nt++)
#pragma unroll
                for (int u = 0; u < 4; u++) s[nt][u] = 0.0f;

#pragma unroll
            for (int kd = 0; kd < 4; kd++) {
#pragma unroll
                for (int p = 0; p < 4; p++) {
                    uint32_t kb[4];
                    ldmx4(kb, Kb + (uint32_t)(p * 16 * AT_STRIDE + kd * 16) * 2 +
                                  lcoK * 2);
                    mma_f16(s[2 * p], qf[kd], kb[0], kb[1]);
                    mma_f16(s[2 * p + 1], qf[kd], kb[2], kb[3]);
                }
            }

            const bool slow = (posS[63] > i0 + w * 16);
            if (!slow) {
#pragma unroll
                for (int nt = 0; nt < 8; nt++)
#pragma unroll
                    for (int u = 0; u < 4; u++) s[nt][u] *= SC;
            } else {
#pragma unroll
                for (int nt = 0; nt < 8; nt++) {
                    const int c0 = nt * 8 + 2 * tq;
#pragma unroll
                    for (int u = 0; u < 4; u++) {
                        const int cl = c0 + (u & 1);
                        const int qrow = (u < 2) ? qr0 : qr1;
                        float v = s[nt][u] * SC;
                        if (posS[cl] > qrow) v = NEGB;
                        s[nt][u] = v;
                    }
                }
            }

            float mx0 = -1e30f, mx1 = -1e30f;
#pragma unroll
            for (int nt = 0; nt < 8; nt++) {
                mx0 = fmaxf(mx0, fmaxf(s[nt][0], s[nt][1]));
                mx1 = fmaxf(mx1, fmaxf(s[nt][2], s[nt][3]));
            }
#pragma unroll
            for (int off = 1; off <= 2; off <<= 1) {
                mx0 = fmaxf(mx0, __shfl_xor_sync(0xffffffffu, mx0, off));
                mx1 = fmaxf(mx1, __shfl_xor_sync(0xffffffffu, mx1, off));
            }
            const float mn0 = fmaxf(m0, mx0), mn1 = fmaxf(m1, mx1);
            const float cr0 = exp2f(m0 - mn0), cr1 = exp2f(m1 - mn1);
            float rs0 = 0.0f, rs1 = 0.0f;
#pragma unroll
            for (int nt = 0; nt < 8; nt++) {
                s[nt][0] = exp2f(s[nt][0] - mn0);
                s[nt][1] = exp2f(s[nt][1] - mn0);
                s[nt][2] = exp2f(s[nt][2] - mn1);
                s[nt][3] = exp2f(s[nt][3] - mn1);
                rs0 += s[nt][0] + s[nt][1];
                rs1 += s[nt][2] + s[nt][3];
            }
#pragma unroll
            for (int off = 1; off <= 2; off <<= 1) {
                rs0 += __shfl_xor_sync(0xffffffffu, rs0, off);
                rs1 += __shfl_xor_sync(0xffffffffu, rs1, off);
            }
            l0 = l0 * cr0 + rs0;
            l1 = l1 * cr1 + rs1;
            m0 = mn0;
            m1 = mn1;
#pragma unroll
            for (int dt = 0; dt < 8; dt++) {
                o[dt][0] *= cr0; o[dt][1] *= cr0;
                o[dt][2] *= cr1; o[dt][3] *= cr1;
            }

#pragma unroll
            for (int kc = 0; kc < 4; kc++) {
                uint32_t ph[4];
                ph[0] = pack_h(s[2 * kc][0], s[2 * kc][1]);
                ph[1] = pack_h(s[2 * kc][2], s[2 * kc][3]);
                ph[2] = pack_h(s[2 * kc + 1][0], s[2 * kc + 1][1]);
                ph[3] = pack_h(s[2 * kc + 1][2], s[2 * kc + 1][3]);
#pragma unroll
                for (int dp = 0; dp < 4; dp++) {
                    uint32_t vb[4];
                    ldmx4t(vb, Vb + (uint32_t)(kc * 16 * AT_STRIDE + dp * 16) * 2 +
                                   lcoV * 2);
                    mma_f16(o[2 * dp], ph, vb[0], vb[1]);
                    mma_f16(o[2 * dp + 1], ph, vb[2], vb[3]);
                }
            }
            __syncthreads();
        }
    }

    const float inv0 = 1.0f / l0, inv1 = 1.0f / l1;
    const bool dg0 = (m0 < -5e8f), dg1 = (m1 < -5e8f);
#pragma unroll
    for (int dt = 0; dt < 8; dt++) {
        const int dd = dt * 8 + 2 * tq;
        float o00 = dg0 ? g_vmean[nh * D_DIM + dd] : o[dt][0] * inv0;
        float o01 = dg0 ? g_vmean[nh * D_DIM + dd + 1] : o[dt][1] * inv0;
        float o10 = dg1 ? g_vmean[nh * D_DIM + dd] : o[dt][2] * inv1;
        float o11 = dg1 ? g_vmean[nh * D_DIM + dd + 1] : o[dt][3] * inv1;
        float2* p0 = (float2*)(out + ((size_t)(nb * SEQ + qr0)) * E_DIM + h * D_DIM + dd);
        float2* p1 = (float2*)(out + ((size_t)(nb * SEQ + qr1)) * E_DIM + h * D_DIM + dd);
        *p0 = make_float2(o00, o01);
        *p1 = make_float2(o10, o11);
    }
}

// ---------------------------------------------------------------------------
// Launch
// ---------------------------------------------------------------------------
extern "C" void kernel_launch(void* const* d_in, const int* in_sizes, int n_in,
                              void* d_out, int out_size)
{
    const float* query = (const float*)d_in[0];
    const float* key   = (const float*)d_in[1];
    const float* value = (const float*)d_in[2];
    const int*   pad   = (const int*)d_in[3];
    const float* Wq = (const float*)d_in[5];
    const float* bq = (const float*)d_in[6];
    const float* Wk = (const float*)d_in[7];
    const float* bk = (const float*)d_in[8];
    const float* Wv = (const float*)d_in[9];
    const float* bv = (const float*)d_in[10];
    float* out = (float*)d_out;

    conv_all_kernel<<<3 * XB + 3 * WB, 256>>>(query, key, value, Wq, Wk, Wv);
    scan_kernel<<<NB, 1024>>>(pad);

    dim3 pgrid(E_DIM / 128, (NB * SEQ) / 128, 3);
    proj_mma_kernel<<<pgrid, 256>>>(bq, bk, bv);

    dim3 v1grid(NHTOT, 8);
    vmean1_kernel<<<v1grid, 256>>>();
    vmean2_kernel<<<NHTOT, 64>>>();

    cudaFuncSetAttribute(attn_mma_kernel, cudaFuncAttributeMaxDynamicSharedMemorySize,
                         AT_SMEM);
    dim3 agrid(SEQ / 128, NHTOT);
    attn_mma_kernel<<<agrid, 256, AT_SMEM>>>(out);
}